// round 12
// baseline (speedup 1.0000x reference)
#include <cuda_runtime.h>
#include <cuda_bf16.h>
#include <math.h>

// ---------------- problem constants ----------------
#define BB   2
#define TT   2048
#define DD   1024
#define HH   8
#define DH   128
#define KS   512
#define KRR  16
#define CH   128
#define NCH  16
#define ETA_C    0.1f
#define FORGET_C 0.01f
#define SCALE_C  0.08838834764831845f

#define BHT (BB*HH*TT)
#define BH  (BB*HH)
#define NBLK 128

// ---------------- scratch ----------------
__device__ float g_q   [BB*HH*TT*DH];
__device__ float g_k   [BB*HH*TT*DH];
__device__ float g_v   [BB*HH*TT*DH];
__device__ float g_khat[BB*HH*TT*DH];
__device__ float g_reads[BB*HH*TT*DH];
__device__ float g_local[BB*HH*TT*DH];
__device__ float g_slotk[BB*HH*KS*DH];
__device__ float g_slotv[BB*HH*KS*DH];
__device__ __nv_bfloat16 g_skh[BB*HH*KS*DH];
__device__ __nv_bfloat16 g_skl[BB*HH*KS*DH];
__device__ __nv_bfloat16 g_qh[BB*HH*TT*DH], g_ql[BB*HH*TT*DH];
__device__ __nv_bfloat16 g_kh[BB*HH*TT*DH], g_kl[BB*HH*TT*DH];
__device__ __nv_bfloat16 g_vh[BB*HH*TT*DH], g_vl[BB*HH*TT*DH];
__device__ __nv_bfloat16 g_khh[BB*HH*TT*DH], g_khl[BB*HH*TT*DH];
__device__ int   g_eidx [BB*HH*CH*KRR];
__device__ float g_ewp  [BB*HH*CH*KRR];
__device__ float g_eproj[BB*HH*CH*KRR];
__device__ unsigned long long g_bar = 0;   // monotonic ticket counter (never reset)

// ---------------- cp.async helpers ----------------
__device__ __forceinline__ void cpa16(void* dst, const void* src)
{
    unsigned d = (unsigned)__cvta_generic_to_shared(dst);
    asm volatile("cp.async.cg.shared.global [%0], [%1], 16;\n"
                 :: "r"(d), "l"(__cvta_generic_to_global(src)));
}
#define CP_COMMIT asm volatile("cp.async.commit_group;\n" ::: "memory")
#define CP_WAIT(n) asm volatile("cp.async.wait_group %0;\n" :: "n"(n) : "memory")

// ---------------- software grid barrier (all NBLK blocks resident) ------
__device__ __forceinline__ void grid_barrier(int tid)
{
    __threadfence();
    __syncthreads();
    if (tid == 0) {
        unsigned long long t = atomicAdd(&g_bar, 1ULL);
        unsigned long long target = (t / NBLK + 1) * (unsigned long long)NBLK;
        while (*(volatile unsigned long long*)&g_bar < target) { }
    }
    __syncthreads();
    __threadfence();
}

// fused A-load for final projection: A = reads + local, head-interleaved
__device__ __forceinline__ float4 fused_load(int row, int col)
{
    int b = row >> 11, t = row & 2047;
    int h = col >> 7,  e = col & 127;
    int idx = (((b*HH + h)*TT) + t)*DH + e;
    float4 r = *(const float4*)&g_reads[idx];
    float4 l = *(const float4*)&g_local[idx];
    return make_float4(r.x+l.x, r.y+l.y, r.z+l.z, r.w+l.w);
}

// ---------------- bf16-split MMA primitives ----------------
__device__ __forceinline__ void mma16816(float* d, const unsigned* a, const unsigned* b)
{
    asm volatile(
        "mma.sync.aligned.m16n8k16.row.col.f32.bf16.bf16.f32 "
        "{%0,%1,%2,%3}, {%4,%5,%6,%7}, {%8,%9}, {%0,%1,%2,%3};\n"
        : "+f"(d[0]), "+f"(d[1]), "+f"(d[2]), "+f"(d[3])
        : "r"(a[0]), "r"(a[1]), "r"(a[2]), "r"(a[3]), "r"(b[0]), "r"(b[1]));
}

__device__ __forceinline__ void ldsm4(unsigned* r, unsigned addr)
{
    asm volatile("ldmatrix.sync.aligned.m8n8.x4.shared.b16 {%0,%1,%2,%3}, [%4];"
                 : "=r"(r[0]), "=r"(r[1]), "=r"(r[2]), "=r"(r[3]) : "r"(addr));
}
__device__ __forceinline__ void ldsm2(unsigned* r, unsigned addr)
{
    asm volatile("ldmatrix.sync.aligned.m8n8.x2.shared.b16 {%0,%1}, [%2];"
                 : "=r"(r[0]), "=r"(r[1]) : "r"(addr));
}

__device__ __forceinline__ void pack_hl(float a, float b, unsigned& h, unsigned& l)
{
    __nv_bfloat16 ha = __float2bfloat16(a), hb = __float2bfloat16(b);
    __nv_bfloat16 la = __float2bfloat16(a - __bfloat162float(ha));
    __nv_bfloat16 lb = __float2bfloat16(b - __bfloat162float(hb));
    h = (unsigned)__bfloat16_as_ushort(ha) | ((unsigned)__bfloat16_as_ushort(hb) << 16);
    l = (unsigned)__bfloat16_as_ushort(la) | ((unsigned)__bfloat16_as_ushort(lb) << 16);
}

__device__ __forceinline__ void split_store(float4 v, __nv_bfloat16* Hp, __nv_bfloat16* Lp)
{
    unsigned h0, l0, h1, l1;
    pack_hl(v.x, v.y, h0, l0);
    pack_hl(v.z, v.w, h1, l1);
    *(unsigned*)(Hp)     = h0; *(unsigned*)(Hp + 2) = h1;
    *(unsigned*)(Lp)     = l0; *(unsigned*)(Lp + 2) = l1;
}

__device__ __forceinline__ void write_c2(int mode, float* Cout, int Ncols,
                                         int row, int col, float v0, float v1)
{
    if (mode == 0) {
        int which = col >> 10;
        int h = (col >> 7) & 7;
        int e = col & 127;
        int b = row >> 11;
        int t = row & 2047;
        int idx = (((b*HH + h)*TT) + t)*DH + e;
        float* dst = (which == 0) ? g_q : (which == 1) ? g_k : g_v;
        *(float2*)&dst[idx] = make_float2(v0, v1);
        __nv_bfloat16* dh = (which == 0) ? g_qh : (which == 1) ? g_kh : g_vh;
        __nv_bfloat16* dl = (which == 0) ? g_ql : (which == 1) ? g_kl : g_vl;
        unsigned hp, lp; pack_hl(v0, v1, hp, lp);
        *(unsigned*)&dh[idx] = hp;
        *(unsigned*)&dl[idx] = lp;
    } else {
        *(float2*)&Cout[row * Ncols + col] = make_float2(v0, v1);
    }
}

// ---------------- big GEMMs (qkv / out-proj), bf16-split ----------------
__global__ __launch_bounds__(256)
void mma_gemm(const float* __restrict__ A, const float* __restrict__ Bm,
              const float* __restrict__ bias, float* __restrict__ Cout,
              int Kdim, int mode, int Ncols)
{
    __shared__ __nv_bfloat16 Ah[128][24], Al[128][24];
    __shared__ __nv_bfloat16 Bh[128][24], Bl[128][24];

    int bm = blockIdx.y * 128, bn = blockIdx.x * 128;
    int tid = threadIdx.x;
    int warp = tid >> 5, lane = tid & 31;
    int wm = warp >> 2, wn = warp & 3;
    int lr = lane >> 2, lc = lane & 3;

    int srow = tid >> 1;
    int sk   = (tid & 1) * 8;

    float acc[4][4][4];
#pragma unroll
    for (int i = 0; i < 4; i++)
#pragma unroll
        for (int j = 0; j < 4; j++)
#pragma unroll
            for (int r = 0; r < 4; r++) acc[i][j][r] = 0.f;

    int arow = bm + srow, brow = bn + srow;
    float4 a0v = mode ? fused_load(arow, sk)     : *(const float4*)(A + arow*Kdim + sk);
    float4 a1v = mode ? fused_load(arow, sk + 4) : *(const float4*)(A + arow*Kdim + sk + 4);
    float4 b0v = *(const float4*)(Bm + brow*Kdim + sk);
    float4 b1v = *(const float4*)(Bm + brow*Kdim + sk + 4);

    for (int kp = 0; kp < Kdim; kp += 16) {
        __syncthreads();
        split_store(a0v, &Ah[srow][sk],   &Al[srow][sk]);
        split_store(a1v, &Ah[srow][sk+4], &Al[srow][sk+4]);
        split_store(b0v, &Bh[srow][sk],   &Bl[srow][sk]);
        split_store(b1v, &Bh[srow][sk+4], &Bl[srow][sk+4]);
        __syncthreads();
        if (kp + 16 < Kdim) {
            int kn = kp + 16;
            a0v = mode ? fused_load(arow, kn + sk)     : *(const float4*)(A + arow*Kdim + kn + sk);
            a1v = mode ? fused_load(arow, kn + sk + 4) : *(const float4*)(A + arow*Kdim + kn + sk + 4);
            b0v = *(const float4*)(Bm + brow*Kdim + kn + sk);
            b1v = *(const float4*)(Bm + brow*Kdim + kn + sk + 4);
        }

        unsigned Afh[4][4], Afl[4][4], Bfh[4][2], Bfl[4][2];
#pragma unroll
        for (int mi = 0; mi < 4; mi++) {
            int r = wm*64 + mi*16 + lr;
            Afh[mi][0] = *(const unsigned*)&Ah[r][lc*2];
            Afh[mi][1] = *(const unsigned*)&Ah[r+8][lc*2];
            Afh[mi][2] = *(const unsigned*)&Ah[r][lc*2+8];
            Afh[mi][3] = *(const unsigned*)&Ah[r+8][lc*2+8];
            Afl[mi][0] = *(const unsigned*)&Al[r][lc*2];
            Afl[mi][1] = *(const unsigned*)&Al[r+8][lc*2];
            Afl[mi][2] = *(const unsigned*)&Al[r][lc*2+8];
            Afl[mi][3] = *(const unsigned*)&Al[r+8][lc*2+8];
        }
#pragma unroll
        for (int ni = 0; ni < 4; ni++) {
            int n = wn*32 + ni*8 + lr;
            Bfh[ni][0] = *(const unsigned*)&Bh[n][lc*2];
            Bfh[ni][1] = *(const unsigned*)&Bh[n][lc*2+8];
            Bfl[ni][0] = *(const unsigned*)&Bl[n][lc*2];
            Bfl[ni][1] = *(const unsigned*)&Bl[n][lc*2+8];
        }
#pragma unroll
        for (int mi = 0; mi < 4; mi++)
#pragma unroll
            for (int ni = 0; ni < 4; ni++) {
                mma16816(acc[mi][ni], Afh[mi], Bfh[ni]);
                mma16816(acc[mi][ni], Afh[mi], Bfl[ni]);
                mma16816(acc[mi][ni], Afl[mi], Bfh[ni]);
            }
    }

#pragma unroll
    for (int mi = 0; mi < 4; mi++)
#pragma unroll
        for (int ni = 0; ni < 4; ni++) {
            int row0 = bm + wm*64 + mi*16 + lr;
            int col0 = bn + wn*32 + ni*8 + lc*2;
            write_c2(mode, Cout, Ncols, row0,   col0, acc[mi][ni][0] + bias[col0],
                                               acc[mi][ni][1] + bias[col0+1]);
            write_c2(mode, Cout, Ncols, row0+8, col0, acc[mi][ni][2] + bias[col0],
                                               acc[mi][ni][3] + bias[col0+1]);
        }
}

// ---------------- dual top-16 + softmax (two independent rows) ----------
__device__ __forceinline__
void topk16_dual(const float* __restrict__ r0p, const float* __restrict__ r1p,
                 int lane, int* oi0, float* op0, int* oi1, float* op1)
{
    float v0[16], v1[16];
#pragma unroll
    for (int i = 0; i < 16; i++) { v0[i] = r0p[i*32 + lane]; v1[i] = r1p[i*32 + lane]; }
    float m0 = 0.f, s0 = 0.f, m1 = 0.f, s1 = 0.f;
#pragma unroll
    for (int it = 0; it < 16; it++) {
        float bv0 = -INFINITY, bv1 = -INFINITY; int bl0 = 0, bl1 = 0;
#pragma unroll
        for (int i = 0; i < 16; i++) {
            if (v0[i] > bv0) { bv0 = v0[i]; bl0 = i; }
            if (v1[i] > bv1) { bv1 = v1[i]; bl1 = i; }
        }
        int bi0 = bl0*32 + lane, bi1 = bl1*32 + lane;
#pragma unroll
        for (int off = 16; off; off >>= 1) {
            float ov0 = __shfl_xor_sync(0xffffffffu, bv0, off);
            int   oj0 = __shfl_xor_sync(0xffffffffu, bi0, off);
            float ov1 = __shfl_xor_sync(0xffffffffu, bv1, off);
            int   oj1 = __shfl_xor_sync(0xffffffffu, bi1, off);
            if (ov0 > bv0 || (ov0 == bv0 && oj0 < bi0)) { bv0 = ov0; bi0 = oj0; }
            if (ov1 > bv1 || (ov1 == bv1 && oj1 < bi1)) { bv1 = ov1; bi1 = oj1; }
        }
        if (it == 0) { m0 = bv0; m1 = bv1; }
        op0[it] = __expf(bv0 - m0); s0 += op0[it]; oi0[it] = bi0;
        op1[it] = __expf(bv1 - m1); s1 += op1[it]; oi1[it] = bi1;
        int wl0 = bi0 & 31, wc0 = bi0 >> 5;
        int wl1 = bi1 & 31, wc1 = bi1 >> 5;
#pragma unroll
        for (int i = 0; i < 16; i++) {
            if (lane == wl0 && i == wc0) v0[i] = -INFINITY;
            if (lane == wl1 && i == wc1) v1[i] = -INFINITY;
        }
    }
    float i0 = 1.0f / s0, i1 = 1.0f / s1;
#pragma unroll
    for (int it = 0; it < 16; it++) { op0[it] *= i0; op1[it] *= i1; }
}

// ---------------- persistent scan kernel --------------------------------
// grid 128 blocks (qt = bid&7, bh = bid>>3), 512 threads, ~150KB smem.
// phase 0: init slots + khat.  Then per chunk: A (scores/topk/read/proj),
// barrier, B (slot update), barrier.
#define AP 136
#define SP 520
#define CQK_SMEM (32*AP*2*2 + 2*64*AP*2*2 + 32*SP*4)
__global__ __launch_bounds__(512)
void scan_kernel(const float* __restrict__ Sinit, const float* __restrict__ temp_ptr)
{
    extern __shared__ char smemraw[];
    __nv_bfloat16* Ah = (__nv_bfloat16*)smemraw;       // [32][AP]
    __nv_bfloat16* Al = Ah + 32*AP;
    __nv_bfloat16* Bbase = Al + 32*AP;                 // 2 stages x (Bh|Bl)[64][AP]
    float* scores = (float*)(Bbase + 2*2*64*AP);       // [32][SP], reused in phase B

    int bid = blockIdx.x;
    int qt = bid & 7, bh = bid >> 3;
    int tid = threadIdx.x;
    int warp = tid >> 5, lane = tid & 31;
    int wm = warp >> 3, wn = warp & 7;

    // ---- phase 0a: init slots (64 slot-rows per block) ----
#pragma unroll 1
    for (int i = 0; i < 4; i++) {
        int wid = bid*64 + warp*4 + i;
        int ibh = wid >> 9, s = wid & 511, h = ibh & 7;
        const float* src = Sinit + s*DD + h*DH;
        float v[4]; float nn = 0.f;
#pragma unroll
        for (int j = 0; j < 4; j++) { v[j] = src[lane + 32*j]; nn += v[j]*v[j]; }
#pragma unroll
        for (int off = 16; off; off >>= 1) nn += __shfl_xor_sync(0xffffffffu, nn, off);
        float inv = 1.0f / (sqrtf(nn) + 1e-6f);
        int rb = (ibh*KS + s)*DH;
#pragma unroll
        for (int j = 0; j < 4; j++) {
            int e = lane + 32*j;
            float kk = v[j]*inv;
            g_slotk[rb + e] = kk;
            g_slotv[rb + e] = v[j];
            __nv_bfloat16 hv = __float2bfloat16(kk);
            g_skh[rb + e] = hv;
            g_skl[rb + e] = __float2bfloat16(kk - __bfloat162float(hv));
        }
    }
    // ---- phase 0b: khat (256 token rows per block) ----
#pragma unroll 1
    for (int i = 0; i < 16; i++) {
        int row = bid*256 + warp*16 + i;
        int base = row * DH;
        float v[4]; float nn = 0.f;
#pragma unroll
        for (int j = 0; j < 4; j++) { v[j] = g_k[base + lane + 32*j]; nn += v[j]*v[j]; }
#pragma unroll
        for (int off = 16; off; off >>= 1) nn += __shfl_xor_sync(0xffffffffu, nn, off);
        float inv = 1.0f / (sqrtf(nn) + 1e-6f);
#pragma unroll
        for (int j = 0; j < 4; j++) {
            int e = base + lane + 32*j;
            float kv = v[j]*inv;
            g_khat[e] = kv;
            __nv_bfloat16 hv = __float2bfloat16(kv);
            g_khh[e] = hv;
            g_khl[e] = __float2bfloat16(kv - __bfloat162float(hv));
        }
    }
    grid_barrier(tid);

    float fq = SCALE_C / temp_ptr[0];
    int q0 = qt * 16;
    int slotbase = bh*KS;

    // per-warp ldmatrix addresses (A fixed; B offset within stage)
    unsigned aOffH, aOffL, bOff;
    {
        unsigned abase = (unsigned)__cvta_generic_to_shared(Ah);
        unsigned albase = (unsigned)__cvta_generic_to_shared(Al);
        unsigned arow = (wm*16 + (lane & 15))*AP + (lane >> 4)*8;
        aOffH = abase + arow*2;
        aOffL = albase + arow*2;
        bOff = (unsigned)(((wn*8 + (lane & 7))*AP + ((lane >> 3) & 1)*8) * 2);
    }
    unsigned bStage0 = (unsigned)__cvta_generic_to_shared(Bbase);

#pragma unroll 1
    for (int ch = 0; ch < NCH; ch++) {
        int tokrow0 = bh*TT + ch*CH + q0;

        // ===== phase A =====
        {
            int i = tid;          // 32 rows x 16 byte-chunks = 512
            int r = i >> 4, seg = (i & 15)*8;
            int gi = (tokrow0 + (r & 15))*DH + seg;
            const __nv_bfloat16* sh = (r < 16 ? g_qh : g_khh) + gi;
            const __nv_bfloat16* sl = (r < 16 ? g_ql : g_khl) + gi;
            cpa16(&Ah[r*AP + seg], sh);
            cpa16(&Al[r*AP + seg], sl);
        }
        {
            __nv_bfloat16* Bh = Bbase;
            __nv_bfloat16* Bl = Bbase + 64*AP;
#pragma unroll
            for (int i = tid; i < 64*16; i += 512) {
                int row = i >> 4, seg = (i & 15)*8;
                int gi = (slotbase + row)*DH + seg;
                cpa16(&Bh[row*AP + seg], &g_skh[gi]);
                cpa16(&Bl[row*AP + seg], &g_skl[gi]);
            }
        }
        CP_COMMIT;

#pragma unroll 1
        for (int t = 0; t < 8; t++) {
            if (t < 7) {
                __nv_bfloat16* Bh = Bbase + ((t+1)&1)*2*64*AP;
                __nv_bfloat16* Bl = Bh + 64*AP;
#pragma unroll
                for (int i = tid; i < 64*16; i += 512) {
                    int row = i >> 4, seg = (i & 15)*8;
                    int gi = (slotbase + (t+1)*64 + row)*DH + seg;
                    cpa16(&Bh[row*AP + seg], &g_skh[gi]);
                    cpa16(&Bl[row*AP + seg], &g_skl[gi]);
                }
                CP_COMMIT;
                CP_WAIT(1);
            } else {
                CP_WAIT(0);
            }
            __syncthreads();

            unsigned bH = bStage0 + (unsigned)((t&1)*2*64*AP*2) + bOff;
            unsigned bL = bH + (unsigned)(64*AP*2);

            float acc0[4] = {0.f,0.f,0.f,0.f};
            float acc1[4] = {0.f,0.f,0.f,0.f};
#pragma unroll
            for (int kt = 0; kt < 8; kt++) {
                unsigned kb = (unsigned)(kt*32);
                unsigned Afh[4], Afl[4], Bf0[2], Bf1[2];
                ldsm4(Afh, aOffH + kb);
                ldsm4(Afl, aOffL + kb);
                ldsm2(Bf0, bH + kb);
                ldsm2(Bf1, bL + kb);
                float* acc = (kt < 4) ? acc0 : acc1;
                mma16816(acc, Afh, Bf0);
                mma16816(acc, Afh, Bf1);
                mma16816(acc, Afl, Bf0);
            }
            float factor = (wm == 0) ? fq : 1.0f;
            int col = t*64 + wn*8 + (lane & 3)*2;
            int row0 = wm*16 + (lane >> 2);
            *(float2*)&scores[row0*SP + col] =
                make_float2((acc0[0]+acc1[0])*factor, (acc0[1]+acc1[1])*factor);
            *(float2*)&scores[(row0+8)*SP + col] =
                make_float2((acc0[2]+acc1[2])*factor, (acc0[3]+acc1[3])*factor);
            __syncthreads();
        }

        // topk + read / proj. warps 0-7: q rows (2 each); 8-15: khat rows.
        {
            bool isq = warp < 8;
            int qi0 = (warp & 7)*2, qi1 = qi0 + 1;
            int sr0 = isq ? qi0 : (16 + qi0);
            int oi0[16], oi1[16]; float op0[16], op1[16];
            topk16_dual(&scores[sr0*SP], &scores[(sr0+1)*SP], lane, oi0, op0, oi1, op1);

            int tb0 = (tokrow0 + qi0)*DH, tb1 = (tokrow0 + qi1)*DH;

            if (isq) {
                float4 a0 = make_float4(0.f,0.f,0.f,0.f);
                float4 a1 = a0;
#pragma unroll
                for (int k = 0; k < 16; k++) {
                    float4 v0 = *(const float4*)&g_slotv[(slotbase + oi0[k])*DH + lane*4];
                    float4 v1 = *(const float4*)&g_slotv[(slotbase + oi1[k])*DH + lane*4];
                    a0.x += op0[k]*v0.x; a0.y += op0[k]*v0.y; a0.z += op0[k]*v0.z; a0.w += op0[k]*v0.w;
                    a1.x += op1[k]*v1.x; a1.y += op1[k]*v1.y; a1.z += op1[k]*v1.z; a1.w += op1[k]*v1.w;
                }
                *(float4*)&g_reads[tb0 + lane*4] = a0;
                *(float4*)&g_reads[tb1 + lane*4] = a1;
            } else {
                float4 w0 = *(const float4*)&g_v[tb0 + lane*4];
                float4 w1 = *(const float4*)&g_v[tb1 + lane*4];
                int eb0 = (bh*CH + q0 + qi0)*KRR;
                int eb1 = (bh*CH + q0 + qi1)*KRR;
#pragma unroll
                for (int k = 0; k < 16; k++) {
                    float4 k0 = *(const float4*)&g_slotk[(slotbase + oi0[k])*DH + lane*4];
                    float4 k1 = *(const float4*)&g_slotk[(slotbase + oi1[k])*DH + lane*4];
                    float d0 = w0.x*k0.x + w0.y*k0.y + w0.z*k0.z + w0.w*k0.w;
                    float d1 = w1.x*k1.x + w1.y*k1.y + w1.z*k1.z + w1.w*k1.w;
#pragma unroll
                    for (int off = 16; off; off >>= 1) {
                        d0 += __shfl_xor_sync(0xffffffffu, d0, off);
                        d1 += __shfl_xor_sync(0xffffffffu, d1, off);
                    }
                    if (lane == 0) {
                        g_eidx[eb0 + k] = oi0[k]; g_ewp[eb0 + k] = op0[k]; g_eproj[eb0 + k] = d0;
                        g_eidx[eb1 + k] = oi1[k]; g_ewp[eb1 + k] = op1[k]; g_eproj[eb1 + k] = d1;
                    }
                }
            }
        }
        grid_barrier(tid);

        // ===== phase B: slot update (slots qt*64 .. +63, 4/warp) =====
        {
            int*   sidx = (int*)scores;
            float* swp  = (float*)scores + CH*KRR;
            float* sprj = (float*)scores + 2*CH*KRR;
            int ebase = bh*CH*KRR;
#pragma unroll
            for (int j = tid; j < CH*KRR; j += 512) {
                sidx[j] = g_eidx[ebase + j];
                swp[j]  = g_ewp[ebase + j];
                sprj[j] = g_eproj[ebase + j];
            }
            __syncthreads();

            int tokbase = (bh*TT + ch*CH)*DH;
#pragma unroll 1
            for (int sl = 0; sl < 4; sl++) {
                int s = qt*64 + warp*4 + sl;
                float accv[4] = {0,0,0,0};
                float acck[4] = {0,0,0,0};
                float swpsum = 0.f, swpp = 0.f;
#pragma unroll 1
                for (int b0 = 0; b0 < CH*KRR; b0 += 32) {
                    bool mt = (sidx[b0 + lane] == s);
                    unsigned bal = __ballot_sync(0xffffffffu, mt);
                    while (bal) {
                        int jj = b0 + (__ffs(bal) - 1);
                        bal &= bal - 1;
                        float wp = swp[jj];
                        float pj = sprj[jj];
                        int cc = jj >> 4;
                        const float* vr = g_v    + tokbase + cc*DH;
                        const float* kr = g_khat + tokbase + cc*DH;
#pragma unroll
                        for (int i = 0; i < 4; i++) {
                            int e = lane + 32*i;
                            accv[i] += wp * vr[e];
                            acck[i] += wp * kr[e];
                        }
                        swpsum += wp;
                        swpp   += wp * pj;
                    }
                }
                int rb = (bh*KS + s)*DH;
                float* kd = g_slotk + rb;
                float* vd = g_slotv + rb;
                float nk[4]; float nsum = 0.f;
#pragma unroll
                for (int i = 0; i < 4; i++) {
                    int e = lane + 32*i;
                    float ok = kd[e];
                    float nv = (1.0f - FORGET_C) * vd[e] + ETA_C * (accv[i] - swpp * ok);
                    vd[e] = nv;
                    nk[i] = ok + ETA_C * (acck[i] - swpsum * ok);
                    nsum += nk[i]*nk[i];
                }
#pragma unroll
                for (int off = 16; off; off >>= 1) nsum += __shfl_xor_sync(0xffffffffu, nsum, off);
                float inv = 1.0f / (sqrtf(nsum) + 1e-6f);
#pragma unroll
                for (int i = 0; i < 4; i++) {
                    int e = lane + 32*i;
                    float val = nk[i]*inv;
                    kd[e] = val;
                    __nv_bfloat16 hv = __float2bfloat16(val);
                    g_skh[rb + e] = hv;
                    g_skl[rb + e] = __float2bfloat16(val - __bfloat162float(hv));
                }
            }
        }
        grid_barrier(tid);
    }
}

// ---------------- local sliding-window attention (tensor cores) --------
#define LKP 136
#define LSMEM (4*64*LKP*2)
__global__ __launch_bounds__(128)
void local_mma_kernel()
{
    extern __shared__ __nv_bfloat16 lsm[];
    __nv_bfloat16* Ksh = lsm;              // [64][LKP]
    __nv_bfloat16* Ksl = Ksh + 64*LKP;
    __nv_bfloat16* Vsh = Ksl + 64*LKP;     // [64][LKP]
    __nv_bfloat16* Vsl = Vsh + 64*LKP;
    __nv_bfloat16* Qh = Ksh;               // Q staged transiently in K region
    __nv_bfloat16* Ql = Ksl;

    int q0 = blockIdx.x * 64, bh = blockIdx.y;
    int tid = threadIdx.x, warp = tid >> 5, lane = tid & 31;

    for (int i = tid; i < 64*16; i += 128) {
        int r = i >> 4, seg = (i & 15)*8;
        int gi = (bh*TT + q0 + r)*DH + seg;
        *(uint4*)&Qh[r*LKP + seg] = *(const uint4*)&g_qh[gi];
        *(uint4*)&Ql[r*LKP + seg] = *(const uint4*)&g_ql[gi];
    }
    __syncthreads();

    unsigned aqh[8][4], aql[8][4];
    int r0 = warp*16 + (lane >> 2);
#pragma unroll
    for (int kf = 0; kf < 8; kf++) {
        int c = kf*16 + (lane & 3)*2;
        aqh[kf][0] = *(const unsigned*)&Qh[r0*LKP + c];
        aqh[kf][1] = *(const unsigned*)&Qh[(r0+8)*LKP + c];
        aqh[kf][2] = *(const unsigned*)&Qh[r0*LKP + c + 8];
        aqh[kf][3] = *(const unsigned*)&Qh[(r0+8)*LKP + c + 8];
        aql[kf][0] = *(const unsigned*)&Ql[r0*LKP + c];
        aql[kf][1] = *(const unsigned*)&Ql[(r0+8)*LKP + c];
        aql[kf][2] = *(const unsigned*)&Ql[r0*LKP + c + 8];
        aql[kf][3] = *(const unsigned*)&Ql[(r0+8)*LKP + c + 8];
    }

    float m0 = -1e30f, l0 = 0.f, m1 = -1e30f, l1 = 0.f;
    float o[16][4];
#pragma unroll
    for (int i = 0; i < 16; i++)
#pragma unroll
        for (int r = 0; r < 4; r++) o[i][r] = 0.f;

    int qg0 = q0 + warp*16 + (lane >> 2);
    int qg1 = qg0 + 8;
    int kstart = q0 - 512; if (kstart < 0) kstart = 0;

    unsigned vbh = (unsigned)__cvta_generic_to_shared(Vsh);
    unsigned vbl = (unsigned)__cvta_generic_to_shared(Vsl);

#pragma unroll 1
    for (int kt = kstart; kt <= q0; kt += 64) {
        __syncthreads();
        for (int i = tid; i < 64*16; i += 128) {
            int r = i >> 4, seg = (i & 15)*8;
            int gi = (bh*TT + kt + r)*DH + seg;
            cpa16(&Ksh[r*LKP + seg], &g_kh[gi]);
            cpa16(&Ksl[r*LKP + seg], &g_kl[gi]);
            cpa16(&Vsh[r*LKP + seg], &g_vh[gi]);
            cpa16(&Vsl[r*LKP + seg], &g_vl[gi]);
        }
        CP_COMMIT;
        CP_WAIT(0);
        __syncthreads();

        float s[8][4];
#pragma unroll
        for (int n = 0; n < 8; n++)
#pragma unroll
            for (int r = 0; r < 4; r++) s[n][r] = 0.f;
#pragma unroll
        for (int kf = 0; kf < 8; kf++) {
            int c = kf*16 + (lane & 3)*2;
#pragma unroll
            for (int nf = 0; nf < 8; nf++) {
                int key = nf*8 + (lane >> 2);
                unsigned b0[2], b1[2];
                b0[0] = *(const unsigned*)&Ksh[key*LKP + c];
                b0[1] = *(const unsigned*)&Ksh[key*LKP + c + 8];
                b1[0] = *(const unsigned*)&Ksl[key*LKP + c];
                b1[1] = *(const unsigned*)&Ksl[key*LKP + c + 8];
                mma16816(s[nf], aqh[kf], b0);
                mma16816(s[nf], aqh[kf], b1);
                mma16816(s[nf], aql[kf], b0);
            }
        }

        float rm0 = -1e30f, rm1 = -1e30f;
#pragma unroll
        for (int nf = 0; nf < 8; nf++) {
            int kgb = kt + nf*8 + (lane & 3)*2;
#pragma unroll
            for (int e = 0; e < 4; e++) {
                int kg = kgb + (e & 1);
                int qg = (e < 2) ? qg0 : qg1;
                float sv = s[nf][e] * SCALE_C;
                bool ok = (kg <= qg) && (kg > qg - 512);
                sv = ok ? sv : -1e30f;
                s[nf][e] = sv;
                if (e < 2) rm0 = fmaxf(rm0, sv); else rm1 = fmaxf(rm1, sv);
            }
        }
        rm0 = fmaxf(rm0, __shfl_xor_sync(0xffffffffu, rm0, 1));
        rm0 = fmaxf(rm0, __shfl_xor_sync(0xffffffffu, rm0, 2));
        rm1 = fmaxf(rm1, __shfl_xor_sync(0xffffffffu, rm1, 1));
        rm1 = fmaxf(rm1, __shfl_xor_sync(0xffffffffu, rm1, 2));
        float mn0 = fmaxf(m0, rm0), mn1 = fmaxf(m1, rm1);
        float c0 = __expf(m0 - mn0), c1 = __expf(m1 - mn1);
        m0 = mn0; m1 = mn1;

        float ps0 = 0.f, ps1 = 0.f;
#pragma unroll
        for (int nf = 0; nf < 8; nf++)
#pragma unroll
            for (int e = 0; e < 4; e++) {
                float sv = s[nf][e];
                float p = __expf(sv - ((e < 2) ? mn0 : mn1));
                p = (sv > -1e29f) ? p : 0.f;
                s[nf][e] = p;
                if (e < 2) ps0 += p; else ps1 += p;
            }
        ps0 += __shfl_xor_sync(0xffffffffu, ps0, 1);
        ps0 += __shfl_xor_sync(0xffffffffu, ps0, 2);
        ps1 += __shfl_xor_sync(0xffffffffu, ps1, 1);
        ps1 += __shfl_xor_sync(0xffffffffu, ps1, 2);
        l0 = l0*c0 + ps0;
        l1 = l1*c1 + ps1;

#pragma unroll
        for (int n = 0; n < 16; n++) {
            o[n][0] *= c0; o[n][1] *= c0; o[n][2] *= c1; o[n][3] *= c1;
        }

        unsigned ph[4][4], pl[4][4];
#pragma unroll
        for (int kf2 = 0; kf2 < 4; kf2++) {
            pack_hl(s[2*kf2][0],   s[2*kf2][1],   ph[kf2][0], pl[kf2][0]);
            pack_hl(s[2*kf2][2],   s[2*kf2][3],   ph[kf2][1], pl[kf2][1]);
            pack_hl(s[2*kf2+1][0], s[2*kf2+1][1], ph[kf2][2], pl[kf2][2]);
            pack_hl(s[2*kf2+1][2], s[2*kf2+1][3], ph[kf2][3], pl[kf2][3]);
        }

#pragma unroll
        for (int nf2 = 0; nf2 < 16; nf2++) {
#pragma unroll
            for (int kf2 = 0; kf2 < 4; kf2++) {
                unsigned off = ((unsigned)((kf2*16 + (lane & 15))*LKP + nf2*8)) * 2u;
                unsigned bv[2], bw[2];
                asm volatile(
                    "ldmatrix.sync.aligned.m8n8.x2.trans.shared.b16 {%0,%1}, [%2];"
                    : "=r"(bv[0]), "=r"(bv[1]) : "r"(vbh + off));
                asm volatile(
                    "ldmatrix.sync.aligned.m8n8.x2.trans.shared.b16 {%0,%1}, [%2];"
                    : "=r"(bw[0]), "=r"(bw[1]) : "r"(vbl + off));
                mma16816(o[nf2], ph[kf2], bv);
                mma16816(o[nf2], pl[kf2], bv);
                mma16816(o[nf2], ph[kf2], bw);
            }
        }
    }

    float iv0 = 1.0f / l0, iv1 = 1.0f / l1;
    float* out0 = g_local + (bh*TT + qg0)*DH;
    float* out1 = g_local + (bh*TT + qg1)*DH;
#pragma unroll
    for (int n = 0; n < 16; n++) {
        int col = n*8 + (lane & 3)*2;
        *(float2*)(out0 + col) = make_float2(o[n][0]*iv0, o[n][1]*iv0);
        *(float2*)(out1 + col) = make_float2(o[n][2]*iv1, o[n][3]*iv1);
    }
}

// ---------------- launch ----------------
extern "C" void kernel_launch(void* const* d_in, const int* in_sizes, int n_in,
                              void* d_out, int out_size)
{
    const float* x     = (const float*)d_in[0];
    const float* Wqkv  = (const float*)d_in[1];
    const float* bqkv  = (const float*)d_in[2];
    const float* Wo    = (const float*)d_in[3];
    const float* bo    = (const float*)d_in[4];
    const float* Sinit = (const float*)d_in[5];
    const float* temp  = (const float*)d_in[6];
    float* out = (float*)d_out;

    cudaFuncSetAttribute(scan_kernel,
                         cudaFuncAttributeMaxDynamicSharedMemorySize, CQK_SMEM);
    cudaFuncSetAttribute(local_mma_kernel,
                         cudaFuncAttributeMaxDynamicSharedMemorySize, LSMEM);

    // QKV projection (writes q/k/v + pre-split hi/lo copies)
    mma_gemm<<<dim3(3072/128, (BB*TT)/128), 256>>>(x, Wqkv, bqkv, nullptr, DD, 0, 3072);

    // persistent fused scan: init slots + khat + 16 chunks (A/B phases)
    scan_kernel<<<NBLK, 512, CQK_SMEM>>>(Sinit, temp);

    // local sliding-window attention (tensor cores)
    local_mma_kernel<<<dim3(TT/64, BH), 128, LSMEM>>>();

    // output projection (fused reads+local)
    mma_gemm<<<dim3(DD/128, (BB*TT)/128), 256>>>(nullptr, Wo, bo, out, DD, 1, DD);

    (void)in_sizes; (void)n_in; (void)out_size;
}